// round 5
// baseline (speedup 1.0000x reference)
#include <cuda_runtime.h>
#include <cuda_fp16.h>
#include <cstdint>

#define B_ 16
#define T_ 2048
#define J_ 128
#define D_ 1024

#define N_ATT1 (B_*T_*J_)
#define OFF_ATT2 N_ATT1
#define OFF_G (OFF_ATT2 + B_*T_)

#define TCH 32
#define SCOL 132

// SMEM map (bytes)
#define SM_R1     0        // 64KB: phaseA bufs (2x24KB) / scores fp32 (33.8KB) / phaseC Ut bufs (2x32KB)
#define SM_ATT1H  65536    // 16KB fp16 att1 tile
#define SM_STAGE  81920    // 64*68*4 = 17408
#define SM_WS     99328    // 4KB w1
#define SM_CTS    103424   // 512B
#define SM_HROW   103936   // 256B
#define SMEM_TOT  104448

#define SWZ8(r,c)  (((r)<<7) + (((c) ^ ((r)&7)) << 4))
#define SWZ16(r,c) (((r)<<8) + (((c) ^ ((r)&7)) << 4))

__device__ float g_colterm[B_*J_];
__device__ float g_rowmax[B_*T_];
__device__ float g_agg2[B_*D_];
__device__ float g_agg2p[B_*TCH*D_];
__device__ __half g_uw3h[B_*J_*D_];   // fp16 U .* w3   [b][j][d]
__device__ __half g_uth[B_*D_*J_];    // fp16 U^T       [b][d][j]

__device__ __forceinline__ uint32_t smem_u32(const void* p){
    uint32_t a;
    asm("{ .reg .u64 t; cvta.to.shared.u64 t, %1; cvt.u32.u64 %0, t; }" : "=r"(a) : "l"(p));
    return a;
}
__device__ __forceinline__ void cp16(uint32_t s, const void* g){
    asm volatile("cp.async.cg.shared.global [%0], [%1], 16;" :: "r"(s), "l"(g));
}
#define CP_COMMIT asm volatile("cp.async.commit_group;")
#define CP_WAIT0  asm volatile("cp.async.wait_group 0;")

__device__ __forceinline__ void ldm4(uint32_t r[4], uint32_t a){
    asm volatile("ldmatrix.sync.aligned.m8n8.x4.shared.b16 {%0,%1,%2,%3}, [%4];"
        : "=r"(r[0]), "=r"(r[1]), "=r"(r[2]), "=r"(r[3]) : "r"(a));
}
__device__ __forceinline__ void mma_f16(float c[4], const uint32_t a[4], uint32_t b0, uint32_t b1){
    asm volatile("mma.sync.aligned.m16n8k16.row.col.f32.f16.f16.f32 "
        "{%0,%1,%2,%3}, {%4,%5,%6,%7}, {%8,%9}, {%0,%1,%2,%3};"
        : "+f"(c[0]), "+f"(c[1]), "+f"(c[2]), "+f"(c[3])
        : "r"(a[0]), "r"(a[1]), "r"(a[2]), "r"(a[3]), "r"(b0), "r"(b1));
}

// -------- K0a: colterm --------
__global__ void colterm_kernel(const float* __restrict__ U, const float* __restrict__ w,
                               const float* __restrict__ bias){
    int pair = blockIdx.x * 8 + (threadIdx.x >> 5);
    int lane = threadIdx.x & 31;
    const float* u  = U + (size_t)pair * D_;
    const float* w2 = w + D_;
    float s = 0.f;
    for (int k = lane; k < D_; k += 32) s += u[k] * w2[k];
    #pragma unroll
    for (int o = 16; o; o >>= 1) s += __shfl_xor_sync(0xffffffffu, s, o);
    if (lane == 0) g_colterm[pair] = s + bias[0];
}

// -------- K0b: g_uw3h = fp16(U .* w3) --------
__global__ void uw3h_kernel(const float* __restrict__ U, const float* __restrict__ w){
    int idx = blockIdx.x * 256 + threadIdx.x;     // float4 idx < 524288
    int d4 = idx & 255;
    float4 u = ((const float4*)U)[idx];
    float4 w3 = *(const float4*)(w + 2*D_ + d4*4);
    __half2 h0 = __floats2half2_rn(u.x*w3.x, u.y*w3.y);
    __half2 h1 = __floats2half2_rn(u.z*w3.z, u.w*w3.w);
    ((__half2*)g_uw3h)[idx*2]   = h0;
    ((__half2*)g_uw3h)[idx*2+1] = h1;
}

// -------- K0c: g_uth = fp16(U^T) per batch --------
__global__ void uth_kernel(const float* __restrict__ U){
    __shared__ float t[32][33];
    int b = blockIdx.z, j0 = blockIdx.y*32, d0 = blockIdx.x*32;
    int tx = threadIdx.x, ty = threadIdx.y;   // 32 x 8
    const float* Ub = U + ((size_t)b*J_ + j0)*D_ + d0;
    #pragma unroll
    for (int i = 0; i < 32; i += 8) t[ty+i][tx] = Ub[(size_t)(ty+i)*D_ + tx];
    __syncthreads();
    __half* Tb = g_uth + ((size_t)b*D_ + d0)*J_ + j0;
    #pragma unroll
    for (int i = 0; i < 32; i += 8) Tb[(size_t)(ty+i)*J_ + tx] = __float2half(t[tx][ty+i]);
}

// -------- K1: fused fp16-mma scores + softmax + agg1 --------
__global__ __launch_bounds__(256, 2)
void fusedh_kernel(const float* __restrict__ H, const float* __restrict__ w,
                   float* __restrict__ out){
    extern __shared__ char smc[];
    uint32_t smb = smem_u32(smc);
    float* att1sm = (float*)smc;                      // scores (stride SCOL), aliases R1
    float* stage  = (float*)(smc + SM_STAGE);
    float* ws     = (float*)(smc + SM_WS);
    float* cts    = (float*)(smc + SM_CTS);
    float* hrow   = (float*)(smc + SM_HROW);

    int tid = threadIdx.x;
    int b = blockIdx.y, t0 = blockIdx.x * 64;
    int warp = tid >> 5, lane = tid & 31;
    int wm = warp >> 2, wn = warp & 3;
    int gid = lane >> 2, tig = lane & 3;
    int hr = tid >> 2, hq = tid & 3;                  // loader: row, quarter

    const float*  Hb  = H + (size_t)(b*T_ + t0) * D_;
    const __half* UWb = g_uw3h + (size_t)b * J_ * D_;
    const __half* Utb = g_uth  + (size_t)b * D_ * J_;
    float* Gb = out + OFF_G + (size_t)(b*T_ + t0) * 4096;

    if (tid < 128) cts[tid] = g_colterm[b*J_ + tid];
    #pragma unroll
    for (int i = 0; i < 4; i++) ws[tid + i*256] = w[tid + i*256];

    // cp.async UW chunk 0
    {
        uint32_t dst = smb + 8192;
        int r = tid & 127, ch = tid >> 7;
        #pragma unroll
        for (int i = 0; i < 4; i++){
            int c16 = ch*4 + i;
            cp16(dst + SWZ8(r, c16), UWb + (size_t)r*D_ + c16*8);
        }
        CP_COMMIT;
    }
    float4 hreg[2][4];
    #pragma unroll
    for (int i = 0; i < 4; i++)
        hreg[0][i] = *(const float4*)(Hb + (size_t)hr*D_ + (hq + 4*i)*4);
    __syncthreads();                                   // ws/cts visible

    float hp = 0.f;
    {   // STS H chunk0 (fp16) + hrow partial
        uint32_t bH = smb;
        #pragma unroll
        for (int i = 0; i < 4; i++){
            int f4 = hq + 4*i;
            float4 h = hreg[0][i];
            __half2 p0 = __floats2half2_rn(h.x, h.y), p1 = __floats2half2_rn(h.z, h.w);
            uint32_t a = bH + SWZ8(hr, f4 >> 1) + (f4 & 1)*8;
            asm volatile("st.shared.v2.b32 [%0], {%1,%2};" :: "r"(a),
                         "r"(*(uint32_t*)&p0), "r"(*(uint32_t*)&p1));
            int wb = hq*4 + 16*i;
            hp += h.x*ws[wb] + h.y*ws[wb+1] + h.z*ws[wb+2] + h.w*ws[wb+3];
        }
    }

    float acc[2][4][4];
    #pragma unroll
    for (int i = 0; i < 2; i++)
        #pragma unroll
        for (int j = 0; j < 4; j++)
            #pragma unroll
            for (int k = 0; k < 4; k++) acc[i][j][k] = 0.f;

    // ---- Phase A: S = H @ (U.*w3)^T, K=1024 in 16 chunks of 64 ----
    for (int kci = 0; kci < 16; kci++){
        int cur = kci & 1;
        if (kci < 15){
            #pragma unroll
            for (int i = 0; i < 4; i++)
                hreg[cur^1][i] = *(const float4*)(Hb + (size_t)hr*D_ + (kci+1)*64 + (hq + 4*i)*4);
        }
        CP_WAIT0;
        __syncthreads();
        if (kci < 15){
            uint32_t dst = smb + (cur^1)*24576 + 8192;
            int r = tid & 127, ch = tid >> 7;
            #pragma unroll
            for (int i = 0; i < 4; i++){
                int c16 = ch*4 + i;
                cp16(dst + SWZ8(r, c16), UWb + (size_t)r*D_ + (kci+1)*64 + c16*8);
            }
            CP_COMMIT;
        }
        uint32_t bH = smb + cur*24576, bUW = bH + 8192;
        int lrow = (lane & 7) + ((lane >> 3) & 1)*8;
        #pragma unroll
        for (int kt = 0; kt < 4; kt++){
            int lc16 = kt*2 + (lane >> 4);
            uint32_t af[2][4], bf[2][4];
            ldm4(af[0], bH  + SWZ8(wm*32      + lrow, lc16));
            ldm4(af[1], bH  + SWZ8(wm*32 + 16 + lrow, lc16));
            ldm4(bf[0], bUW + SWZ8(wn*32      + lrow, lc16));
            ldm4(bf[1], bUW + SWZ8(wn*32 + 16 + lrow, lc16));
            #pragma unroll
            for (int mt = 0; mt < 2; mt++)
                #pragma unroll
                for (int nt = 0; nt < 4; nt++)
                    mma_f16(acc[mt][nt], af[mt], bf[nt>>1][nt&1], bf[nt>>1][(nt&1)+2]);
        }
        if (kci < 15){
            uint32_t bH2 = smb + (cur^1)*24576;
            #pragma unroll
            for (int i = 0; i < 4; i++){
                int f4 = hq + 4*i;
                float4 h = hreg[cur^1][i];
                __half2 p0 = __floats2half2_rn(h.x, h.y), p1 = __floats2half2_rn(h.z, h.w);
                uint32_t a = bH2 + SWZ8(hr, f4 >> 1) + (f4 & 1)*8;
                asm volatile("st.shared.v2.b32 [%0], {%1,%2};" :: "r"(a),
                             "r"(*(uint32_t*)&p0), "r"(*(uint32_t*)&p1));
                int wb = (kci+1)*64 + hq*4 + 16*i;
                hp += h.x*ws[wb] + h.y*ws[wb+1] + h.z*ws[wb+2] + h.w*ws[wb+3];
            }
        }
    }
    __syncthreads();                                   // mma done; R1 free

    hp += __shfl_xor_sync(0xffffffffu, hp, 1);
    hp += __shfl_xor_sync(0xffffffffu, hp, 2);
    if (hq == 0) hrow[hr] = hp;

    // scores -> att1sm (row-constant h1 term cancels in softmax over j)
    #pragma unroll
    for (int mt = 0; mt < 2; mt++){
        int r = wm*32 + mt*16 + gid;
        #pragma unroll
        for (int nt = 0; nt < 4; nt++){
            int col = wn*32 + nt*8 + 2*tig;
            att1sm[r*SCOL + col]         = acc[mt][nt][0] + cts[col];
            att1sm[r*SCOL + col + 1]     = acc[mt][nt][1] + cts[col+1];
            att1sm[(r+8)*SCOL + col]     = acc[mt][nt][2] + cts[col];
            att1sm[(r+8)*SCOL + col + 1] = acc[mt][nt][3] + cts[col+1];
        }
    }
    __syncthreads();

    // ---- softmax over j ----
    float* att1out = out + (size_t)(b*T_ + t0) * J_;
    #pragma unroll
    for (int rr = 0; rr < 8; rr++){
        int r = warp*8 + rr;
        float v0 = att1sm[r*SCOL + lane];
        float v1 = att1sm[r*SCOL + lane + 32];
        float v2 = att1sm[r*SCOL + lane + 64];
        float v3 = att1sm[r*SCOL + lane + 96];
        float mx = fmaxf(fmaxf(v0, v1), fmaxf(v2, v3));
        #pragma unroll
        for (int o = 16; o; o >>= 1) mx = fmaxf(mx, __shfl_xor_sync(0xffffffffu, mx, o));
        float e0 = __expf(v0 - mx), e1 = __expf(v1 - mx), e2 = __expf(v2 - mx), e3 = __expf(v3 - mx);
        float s = e0 + e1 + e2 + e3;
        #pragma unroll
        for (int o = 16; o; o >>= 1) s += __shfl_xor_sync(0xffffffffu, s, o);
        float inv = 1.f / s;
        e0 *= inv; e1 *= inv; e2 *= inv; e3 *= inv;
        att1out[(size_t)r*J_ + lane]      = e0;
        att1out[(size_t)r*J_ + lane + 32] = e1;
        att1out[(size_t)r*J_ + lane + 64] = e2;
        att1out[(size_t)r*J_ + lane + 96] = e3;
        att1sm[r*SCOL + lane]      = e0;
        att1sm[r*SCOL + lane + 32] = e1;
        att1sm[r*SCOL + lane + 64] = e2;
        att1sm[r*SCOL + lane + 96] = e3;
        if (lane == 0) g_rowmax[b*T_ + t0 + r] = mx + hrow[r];
    }
    __syncthreads();

    // repack att1 -> fp16 swizzled tile
    {
        uint32_t a1b = smb + SM_ATT1H;
        #pragma unroll
        for (int i = 0; i < 4; i++){
            int c16 = hq + 4*i;
            float4 x = *(float4*)(att1sm + hr*SCOL + c16*8);
            float4 y = *(float4*)(att1sm + hr*SCOL + c16*8 + 4);
            __half2 p0 = __floats2half2_rn(x.x, x.y), p1 = __floats2half2_rn(x.z, x.w);
            __half2 p2 = __floats2half2_rn(y.x, y.y), p3 = __floats2half2_rn(y.z, y.w);
            uint32_t a = a1b + SWZ16(hr, c16);
            asm volatile("st.shared.v4.b32 [%0], {%1,%2,%3,%4};" :: "r"(a),
                         "r"(*(uint32_t*)&p0), "r"(*(uint32_t*)&p1),
                         "r"(*(uint32_t*)&p2), "r"(*(uint32_t*)&p3));
        }
    }
    __syncthreads();

    // prefetch Ut chunk 0
    {
        uint32_t cb = smb;
        #pragma unroll
        for (int i = 0; i < 4; i++){
            int c16 = hq + 4*i;
            cp16(cb + SWZ16(hr, c16), Utb + (size_t)hr*J_ + c16*8);
        }
        CP_COMMIT;
    }

    // ---- Phase C: agg1 = att1 @ U, N=1024 in 16 chunks of 64 ----
    uint32_t a1b = smb + SM_ATT1H;
    int lrow = (lane & 7) + ((lane >> 3) & 1)*8;
    for (int nc = 0; nc < 16; nc++){
        int cur = nc & 1;
        CP_WAIT0;
        __syncthreads();
        if (nc < 15){
            uint32_t cb = smb + (cur^1)*32768;
            const __half* us = Utb + (size_t)(nc+1)*64*J_;
            #pragma unroll
            for (int i = 0; i < 4; i++){
                int c16 = hq + 4*i;
                cp16(cb + SWZ16(hr, c16), us + (size_t)hr*J_ + c16*8);
            }
            CP_COMMIT;
        }
        float ac[2][2][4];
        #pragma unroll
        for (int i = 0; i < 2; i++)
            #pragma unroll
            for (int j = 0; j < 2; j++)
                #pragma unroll
                for (int k = 0; k < 4; k++) ac[i][j][k] = 0.f;
        uint32_t cb = smb + cur*32768;
        #pragma unroll
        for (int kt = 0; kt < 8; kt++){
            int lc16 = kt*2 + (lane >> 4);
            uint32_t af0[4], af1[4], bf[4];
            ldm4(af0, a1b + SWZ16(wm*32      + lrow, lc16));
            ldm4(af1, a1b + SWZ16(wm*32 + 16 + lrow, lc16));
            ldm4(bf,  cb  + SWZ16(wn*16      + lrow, lc16));
            mma_f16(ac[0][0], af0, bf[0], bf[2]);
            mma_f16(ac[0][1], af0, bf[1], bf[3]);
            mma_f16(ac[1][0], af1, bf[0], bf[2]);
            mma_f16(ac[1][1], af1, bf[1], bf[3]);
        }
        #pragma unroll
        for (int mt = 0; mt < 2; mt++)
            #pragma unroll
            for (int nt = 0; nt < 2; nt++){
                int r = wm*32 + mt*16 + gid;
                int col = wn*16 + nt*8 + 2*tig;
                stage[r*68 + col]       = ac[mt][nt][0];
                stage[r*68 + col + 1]   = ac[mt][nt][1];
                stage[(r+8)*68 + col]   = ac[mt][nt][2];
                stage[(r+8)*68 + col+1] = ac[mt][nt][3];
            }
        __syncthreads();
        int dc = nc*64;
        #pragma unroll
        for (int it = 0; it < 4; it++){
            int idx = tid + it*256;                 // < 1024
            int r = idx >> 4, c4 = (idx & 15)*4;
            float4 a4 = *(float4*)(stage + r*68 + c4);
            float4 h4 = *(const float4*)(Hb + (size_t)r*D_ + dc + c4);
            *(float4*)(Gb + (size_t)r*4096 + 1024 + dc + c4) = a4;
            *(float4*)(Gb + (size_t)r*4096 + 2048 + dc + c4) =
                make_float4(a4.x*h4.x, a4.y*h4.y, a4.z*h4.z, a4.w*h4.w);
        }
    }
}

// -------- K2: att2 = softmax_t(rowmax) --------
__global__ void att2_kernel(float* __restrict__ out){
    __shared__ float red[8];
    int b = blockIdx.x, tid = threadIdx.x;
    float v[8];
    #pragma unroll
    for (int i = 0; i < 8; i++) v[i] = g_rowmax[b*T_ + tid + i*256];
    float mx = v[0];
    #pragma unroll
    for (int i = 1; i < 8; i++) mx = fmaxf(mx, v[i]);
    #pragma unroll
    for (int o = 16; o; o >>= 1) mx = fmaxf(mx, __shfl_xor_sync(0xffffffffu, mx, o));
    if ((tid & 31) == 0) red[tid >> 5] = mx;
    __syncthreads();
    mx = red[0];
    #pragma unroll
    for (int i = 1; i < 8; i++) mx = fmaxf(mx, red[i]);
    float e[8], s = 0.f;
    #pragma unroll
    for (int i = 0; i < 8; i++){ e[i] = __expf(v[i] - mx); s += e[i]; }
    #pragma unroll
    for (int o = 16; o; o >>= 1) s += __shfl_xor_sync(0xffffffffu, s, o);
    __syncthreads();
    if ((tid & 31) == 0) red[tid >> 5] = s;
    __syncthreads();
    s = 0.f;
    #pragma unroll
    for (int i = 0; i < 8; i++) s += red[i];
    float inv = 1.f / s;
    #pragma unroll
    for (int i = 0; i < 8; i++) out[OFF_ATT2 + b*T_ + tid + i*256] = e[i] * inv;
}

// -------- K3a: partial agg2 --------
__global__ __launch_bounds__(128)
void agg2p_kernel(const float* __restrict__ H, const float* __restrict__ out){
    int b  = blockIdx.z;
    int tc = blockIdx.y;
    int d4 = blockIdx.x * 128 + threadIdx.x;
    int t0 = tc * (T_/TCH);
    const float* a2 = out + OFF_ATT2 + b*T_ + t0;
    const float4* Hb = (const float4*)(H + ((size_t)b*T_ + t0) * D_) + d4;
    float4 acc = make_float4(0.f, 0.f, 0.f, 0.f);
    #pragma unroll 1
    for (int t = 0; t < T_/TCH; t += 8){
        #pragma unroll
        for (int u = 0; u < 8; u++){
            float a = a2[t+u];
            float4 h = Hb[(size_t)(t+u) * 256];
            acc.x += a*h.x; acc.y += a*h.y; acc.z += a*h.z; acc.w += a*h.w;
        }
    }
    ((float4*)g_agg2p)[((size_t)b*TCH + tc)*256 + d4] = acc;
}

// -------- K3b: reduce --------
__global__ void agg2r_kernel(){
    int idx = blockIdx.x * 256 + threadIdx.x;
    int b = idx >> 10, d = idx & 1023;
    const float* p = g_agg2p + (size_t)b*TCH*D_ + d;
    float acc = 0.f;
    #pragma unroll
    for (int c = 0; c < TCH; c++) acc += p[(size_t)c*D_];
    g_agg2[idx] = acc;
}

// -------- K4: G1 = H ; G4 = H .* agg2 --------
__global__ void g45_kernel(const float* __restrict__ H, float* __restrict__ out){
    int idx = blockIdx.x * 256 + threadIdx.x;
    int d4 = idx & 255;
    int bt = idx >> 8;
    int b  = bt >> 11;
    float4 h = ((const float4*)H)[idx];
    float4 a = ((const float4*)g_agg2)[b*256 + d4];
    float* Gb = out + OFF_G + (size_t)bt*4096;
    *(float4*)(Gb + d4*4) = h;
    *(float4*)(Gb + 3072 + d4*4) = make_float4(h.x*a.x, h.y*a.y, h.z*a.z, h.w*a.w);
}

extern "C" void kernel_launch(void* const* d_in, const int* in_sizes, int n_in,
                              void* d_out, int out_size){
    const float* H    = (const float*)d_in[0];
    const float* U    = (const float*)d_in[1];
    const float* w    = (const float*)d_in[2];
    const float* bias = (const float*)d_in[3];
    float* out = (float*)d_out;

    cudaFuncSetAttribute(fusedh_kernel, cudaFuncAttributeMaxDynamicSharedMemorySize, SMEM_TOT);

    colterm_kernel<<<256, 256>>>(U, w, bias);
    uw3h_kernel<<<B_*J_*D_/4/256, 256>>>(U, w);
    uth_kernel<<<dim3(D_/32, J_/32, B_), dim3(32, 8)>>>(U);
    fusedh_kernel<<<dim3(T_/64, B_), 256, SMEM_TOT>>>(H, w, out);
    att2_kernel<<<B_, 256>>>(out);
    agg2p_kernel<<<dim3(2, TCH, B_), 128>>>(H, out);
    agg2r_kernel<<<B_*D_/256, 256>>>();
    g45_kernel<<<(B_*T_*D_/4)/256, 256>>>(H, out);
}

// round 6
// speedup vs baseline: 1.4901x; 1.4901x over previous
#include <cuda_runtime.h>
#include <cuda_fp16.h>
#include <cstdint>

#define B_ 16
#define T_ 2048
#define J_ 128
#define D_ 1024

#define N_ATT1 (B_*T_*J_)
#define OFF_ATT2 N_ATT1
#define OFF_G (OFF_ATT2 + B_*T_)

#define TCH 32

// scores kernel smem map (bytes)
#define SC_BUF    0        // 2 x (Hh 8KB + UW 16KB) = 49152
#define SC_RED    49152    // 2*64*4 floats = 2KB
#define SC_WS     51200    // 4KB (w1)
#define SC_CTS    55296    // 512B
#define SC_HROW   55808    // 256B
#define SC_TOT    56320

#define SWZ8(r,c)  (((r)<<7) + (((c) ^ ((r)&7)) << 4))
#define SWZ16(r,c) (((r)<<8) + (((c) ^ ((r)&7)) << 4))

__device__ float g_colterm[B_*J_];
__device__ float g_rowmax[B_*T_];
__device__ float g_agg2[B_*D_];
__device__ float g_agg2p[B_*TCH*D_];
__device__ __half g_uw3h[B_*J_*D_];   // fp16 U .* w3   [b][j][d]
__device__ __half g_uth[B_*D_*J_];    // fp16 U^T       [b][d][j]
__device__ __half g_att1h[B_*T_*J_];  // fp16 att1      [b][t][j]

__device__ __forceinline__ uint32_t smem_u32(const void* p){
    uint32_t a;
    asm("{ .reg .u64 t; cvta.to.shared.u64 t, %1; cvt.u32.u64 %0, t; }" : "=r"(a) : "l"(p));
    return a;
}
__device__ __forceinline__ void cp16(uint32_t s, const void* g){
    asm volatile("cp.async.cg.shared.global [%0], [%1], 16;" :: "r"(s), "l"(g));
}
#define CP_COMMIT asm volatile("cp.async.commit_group;")
#define CP_WAIT0  asm volatile("cp.async.wait_group 0;")

__device__ __forceinline__ void ldm4(uint32_t r[4], uint32_t a){
    asm volatile("ldmatrix.sync.aligned.m8n8.x4.shared.b16 {%0,%1,%2,%3}, [%4];"
        : "=r"(r[0]), "=r"(r[1]), "=r"(r[2]), "=r"(r[3]) : "r"(a));
}
__device__ __forceinline__ void mma_f16(float c[4], const uint32_t a[4], uint32_t b0, uint32_t b1){
    asm volatile("mma.sync.aligned.m16n8k16.row.col.f32.f16.f16.f32 "
        "{%0,%1,%2,%3}, {%4,%5,%6,%7}, {%8,%9}, {%0,%1,%2,%3};"
        : "+f"(c[0]), "+f"(c[1]), "+f"(c[2]), "+f"(c[3])
        : "r"(a[0]), "r"(a[1]), "r"(a[2]), "r"(a[3]), "r"(b0), "r"(b1));
}

// -------- K0a: colterm --------
__global__ void colterm_kernel(const float* __restrict__ U, const float* __restrict__ w,
                               const float* __restrict__ bias){
    int pair = blockIdx.x * 8 + (threadIdx.x >> 5);
    int lane = threadIdx.x & 31;
    const float* u  = U + (size_t)pair * D_;
    const float* w2 = w + D_;
    float s = 0.f;
    for (int k = lane; k < D_; k += 32) s += u[k] * w2[k];
    #pragma unroll
    for (int o = 16; o; o >>= 1) s += __shfl_xor_sync(0xffffffffu, s, o);
    if (lane == 0) g_colterm[pair] = s + bias[0];
}

// -------- K0b: g_uw3h = fp16(U .* w3) --------
__global__ void uw3h_kernel(const float* __restrict__ U, const float* __restrict__ w){
    int idx = blockIdx.x * 256 + threadIdx.x;
    int d4 = idx & 255;
    float4 u = ((const float4*)U)[idx];
    float4 w3 = *(const float4*)(w + 2*D_ + d4*4);
    ((__half2*)g_uw3h)[idx*2]   = __floats2half2_rn(u.x*w3.x, u.y*w3.y);
    ((__half2*)g_uw3h)[idx*2+1] = __floats2half2_rn(u.z*w3.z, u.w*w3.w);
}

// -------- K0c: g_uth = fp16(U^T) per batch --------
__global__ void uth_kernel(const float* __restrict__ U){
    __shared__ float t[32][33];
    int b = blockIdx.z, j0 = blockIdx.y*32, d0 = blockIdx.x*32;
    int tx = threadIdx.x, ty = threadIdx.y;   // 32 x 8
    const float* Ub = U + ((size_t)b*J_ + j0)*D_ + d0;
    #pragma unroll
    for (int i = 0; i < 32; i += 8) t[ty+i][tx] = Ub[(size_t)(ty+i)*D_ + tx];
    __syncthreads();
    __half* Tb = g_uth + ((size_t)b*D_ + d0)*J_ + j0;
    #pragma unroll
    for (int i = 0; i < 32; i += 8) Tb[(size_t)(ty+i)*J_ + tx] = __float2half(t[tx][ty+i]);
}

// -------- K1: scores + register softmax --------
__global__ __launch_bounds__(256, 2)
void scores_kernel(const float* __restrict__ H, const float* __restrict__ w,
                   float* __restrict__ out){
    extern __shared__ char smc[];
    uint32_t smb = smem_u32(smc);
    float* red0 = (float*)(smc + SC_RED);            // [64][4]
    float* red1 = red0 + 256;                        // [64][4]
    float* ws   = (float*)(smc + SC_WS);
    float* cts  = (float*)(smc + SC_CTS);
    float* hrow = (float*)(smc + SC_HROW);

    int tid = threadIdx.x;
    int b = blockIdx.y, t0 = blockIdx.x * 64;
    int warp = tid >> 5, lane = tid & 31;
    int wm = warp >> 2, wn = warp & 3;
    int gid = lane >> 2, tig = lane & 3;
    int hr = tid >> 2, hq = tid & 3;

    const float*  Hb  = H + (size_t)(b*T_ + t0) * D_;
    const __half* UWb = g_uw3h + (size_t)b * J_ * D_;

    if (tid < 128) cts[tid] = g_colterm[b*J_ + tid];
    #pragma unroll
    for (int i = 0; i < 4; i++) ws[tid + i*256] = w[tid + i*256];

    // cp.async UW chunk 0
    {
        uint32_t dst = smb + 8192;
        int r = tid & 127, ch = tid >> 7;
        #pragma unroll
        for (int i = 0; i < 4; i++){
            int c16 = ch*4 + i;
            cp16(dst + SWZ8(r, c16), UWb + (size_t)r*D_ + c16*8);
        }
        CP_COMMIT;
    }
    float4 hreg[4];
    #pragma unroll
    for (int i = 0; i < 4; i++)
        hreg[i] = *(const float4*)(Hb + (size_t)hr*D_ + (hq + 4*i)*4);
    __syncthreads();

    float hp = 0.f;
    {   // STS H chunk0 (fp16) + hrow partial
        #pragma unroll
        for (int i = 0; i < 4; i++){
            int f4 = hq + 4*i;
            float4 h = hreg[i];
            __half2 p0 = __floats2half2_rn(h.x, h.y), p1 = __floats2half2_rn(h.z, h.w);
            uint32_t a = smb + SWZ8(hr, f4 >> 1) + (f4 & 1)*8;
            asm volatile("st.shared.v2.b32 [%0], {%1,%2};" :: "r"(a),
                         "r"(*(uint32_t*)&p0), "r"(*(uint32_t*)&p1));
            int wb = hq*4 + 16*i;
            hp += h.x*ws[wb] + h.y*ws[wb+1] + h.z*ws[wb+2] + h.w*ws[wb+3];
        }
    }

    float acc[2][4][4];
    #pragma unroll
    for (int i = 0; i < 2; i++)
        #pragma unroll
        for (int j = 0; j < 4; j++)
            #pragma unroll
            for (int k = 0; k < 4; k++) acc[i][j][k] = 0.f;

    // ---- S = H @ (U.*w3)^T, K=1024 in 16 chunks of 64 ----
    for (int kci = 0; kci < 16; kci++){
        int cur = kci & 1;
        if (kci < 15){
            #pragma unroll
            for (int i = 0; i < 4; i++)
                hreg[i] = *(const float4*)(Hb + (size_t)hr*D_ + (kci+1)*64 + (hq + 4*i)*4);
        }
        CP_WAIT0;
        __syncthreads();
        if (kci < 15){
            uint32_t dst = smb + (cur^1)*24576 + 8192;
            int r = tid & 127, ch = tid >> 7;
            #pragma unroll
            for (int i = 0; i < 4; i++){
                int c16 = ch*4 + i;
                cp16(dst + SWZ8(r, c16), UWb + (size_t)r*D_ + (kci+1)*64 + c16*8);
            }
            CP_COMMIT;
        }
        uint32_t bH = smb + cur*24576, bUW = bH + 8192;
        int lrow = lane & 15;
        #pragma unroll
        for (int kt = 0; kt < 4; kt++){
            int lc16 = kt*2 + (lane >> 4);
            uint32_t af[2][4], bf[2][4];
            ldm4(af[0], bH  + SWZ8(wm*32      + lrow, lc16));
            ldm4(af[1], bH  + SWZ8(wm*32 + 16 + lrow, lc16));
            ldm4(bf[0], bUW + SWZ8(wn*32      + lrow, lc16));
            ldm4(bf[1], bUW + SWZ8(wn*32 + 16 + lrow, lc16));
            #pragma unroll
            for (int mt = 0; mt < 2; mt++)
                #pragma unroll
                for (int nt = 0; nt < 4; nt++)
                    mma_f16(acc[mt][nt], af[mt], bf[nt>>1][nt&1], bf[nt>>1][(nt&1)+2]);
        }
        if (kci < 15){
            uint32_t bH2 = smb + (cur^1)*24576;
            #pragma unroll
            for (int i = 0; i < 4; i++){
                int f4 = hq + 4*i;
                float4 h = hreg[i];
                __half2 p0 = __floats2half2_rn(h.x, h.y), p1 = __floats2half2_rn(h.z, h.w);
                uint32_t a = bH2 + SWZ8(hr, f4 >> 1) + (f4 & 1)*8;
                asm volatile("st.shared.v2.b32 [%0], {%1,%2};" :: "r"(a),
                             "r"(*(uint32_t*)&p0), "r"(*(uint32_t*)&p1));
                int wb = (kci+1)*64 + hq*4 + 16*i;
                hp += h.x*ws[wb] + h.y*ws[wb+1] + h.z*ws[wb+2] + h.w*ws[wb+3];
            }
        }
    }
    hp += __shfl_xor_sync(0xffffffffu, hp, 1);
    hp += __shfl_xor_sync(0xffffffffu, hp, 2);
    __syncthreads();
    if (hq == 0) hrow[hr] = hp;

    // ---- register softmax ----
    int col0 = wn*32 + 2*tig;           // + nt*8
    #pragma unroll
    for (int mt = 0; mt < 2; mt++)
        #pragma unroll
        for (int nt = 0; nt < 4; nt++){
            acc[mt][nt][0] += cts[col0 + nt*8];
            acc[mt][nt][1] += cts[col0 + nt*8 + 1];
            acc[mt][nt][2] += cts[col0 + nt*8];
            acc[mt][nt][3] += cts[col0 + nt*8 + 1];
        }
    float rm[2][2];
    #pragma unroll
    for (int mt = 0; mt < 2; mt++)
        #pragma unroll
        for (int h = 0; h < 2; h++){
            float m = fmaxf(acc[mt][0][2*h], acc[mt][0][2*h+1]);
            #pragma unroll
            for (int nt = 1; nt < 4; nt++)
                m = fmaxf(m, fmaxf(acc[mt][nt][2*h], acc[mt][nt][2*h+1]));
            m = fmaxf(m, __shfl_xor_sync(0xffffffffu, m, 1));
            m = fmaxf(m, __shfl_xor_sync(0xffffffffu, m, 2));
            rm[mt][h] = m;
        }
    if (tig == 0){
        #pragma unroll
        for (int mt = 0; mt < 2; mt++)
            #pragma unroll
            for (int h = 0; h < 2; h++)
                red0[(wm*32 + mt*16 + h*8 + gid)*4 + wn] = rm[mt][h];
    }
    __syncthreads();
    float rs[2][2];
    #pragma unroll
    for (int mt = 0; mt < 2; mt++)
        #pragma unroll
        for (int h = 0; h < 2; h++){
            int r = wm*32 + mt*16 + h*8 + gid;
            float m = fmaxf(fmaxf(red0[r*4], red0[r*4+1]), fmaxf(red0[r*4+2], red0[r*4+3]));
            rm[mt][h] = m;
            float s = 0.f;
            #pragma unroll
            for (int nt = 0; nt < 4; nt++){
                acc[mt][nt][2*h]   = __expf(acc[mt][nt][2*h]   - m);
                acc[mt][nt][2*h+1] = __expf(acc[mt][nt][2*h+1] - m);
                s += acc[mt][nt][2*h] + acc[mt][nt][2*h+1];
            }
            s += __shfl_xor_sync(0xffffffffu, s, 1);
            s += __shfl_xor_sync(0xffffffffu, s, 2);
            rs[mt][h] = s;
        }
    if (tig == 0){
        #pragma unroll
        for (int mt = 0; mt < 2; mt++)
            #pragma unroll
            for (int h = 0; h < 2; h++)
                red1[(wm*32 + mt*16 + h*8 + gid)*4 + wn] = rs[mt][h];
    }
    __syncthreads();
    float* att1out = out + (size_t)(b*T_ + t0) * J_;
    #pragma unroll
    for (int mt = 0; mt < 2; mt++)
        #pragma unroll
        for (int h = 0; h < 2; h++){
            int r = wm*32 + mt*16 + h*8 + gid;
            float inv = 1.f / (red1[r*4] + red1[r*4+1] + red1[r*4+2] + red1[r*4+3]);
            #pragma unroll
            for (int nt = 0; nt < 4; nt++){
                float e0 = acc[mt][nt][2*h] * inv;
                float e1 = acc[mt][nt][2*h+1] * inv;
                int c = col0 + nt*8;
                *(float2*)(att1out + (size_t)r*J_ + c) = make_float2(e0, e1);
                *(__half2*)(g_att1h + (size_t)(b*T_ + t0 + r)*J_ + c) = __floats2half2_rn(e0, e1);
            }
            if (wn == 0 && tig == 0)
                g_rowmax[b*T_ + t0 + r] = rm[mt][h] + hrow[r];
        }
}

// -------- K1b: agg1 = att1 @ U (GEMM) + G2/G3 writes --------
__global__ __launch_bounds__(256, 3)
void agg1_kernel(const float* __restrict__ H, float* __restrict__ out){
    extern __shared__ char smc[];
    uint32_t smb = smem_u32(smc);
    int tid = threadIdx.x;
    int b  = blockIdx.z;
    int m0 = blockIdx.y * 128;       // t rows
    int n0 = blockIdx.x * 64;        // d cols
    int warp = tid >> 5, lane = tid & 31;
    int wm = warp >> 1, wn = warp & 1;
    int gid = lane >> 2, tig = lane & 3;

    const __half* Ab = g_att1h + (size_t)(b*T_ + m0) * J_;
    const __half* Bb = g_uth + ((size_t)b*D_ + n0) * J_;

    // load A tile 128x128 fp16 (32KB) + B tile 64x128 fp16 (16KB)
    #pragma unroll
    for (int i = 0; i < 8; i++){
        int idx = tid + i*256;       // < 2048
        int r = idx >> 4, c = idx & 15;
        cp16(smb + SWZ16(r, c), Ab + (size_t)r*J_ + c*8);
    }
    #pragma unroll
    for (int i = 0; i < 4; i++){
        int idx = tid + i*256;       // < 1024
        int r = idx >> 4, c = idx & 15;
        cp16(smb + 32768 + SWZ16(r, c), Bb + (size_t)r*J_ + c*8);
    }
    CP_COMMIT;

    float acc[2][4][4];
    #pragma unroll
    for (int i = 0; i < 2; i++)
        #pragma unroll
        for (int j = 0; j < 4; j++)
            #pragma unroll
            for (int k = 0; k < 4; k++) acc[i][j][k] = 0.f;

    CP_WAIT0;
    __syncthreads();

    int lrow = lane & 15;
    uint32_t aB = smb, bB = smb + 32768;
    #pragma unroll
    for (int kt = 0; kt < 8; kt++){
        int lc16 = kt*2 + (lane >> 4);
        uint32_t af[2][4], bf[2][4];
        ldm4(af[0], aB + SWZ16(wm*32      + lrow, lc16));
        ldm4(af[1], aB + SWZ16(wm*32 + 16 + lrow, lc16));
        ldm4(bf[0], bB + SWZ16(wn*32      + lrow, lc16));
        ldm4(bf[1], bB + SWZ16(wn*32 + 16 + lrow, lc16));
        #pragma unroll
        for (int mt = 0; mt < 2; mt++)
            #pragma unroll
            for (int nt = 0; nt < 4; nt++)
                mma_f16(acc[mt][nt], af[mt], bf[nt>>1][nt&1], bf[nt>>1][(nt&1)+2]);
    }

    const float* Hb = H + (size_t)(b*T_ + m0) * D_;
    float* Gb = out + OFF_G + (size_t)(b*T_ + m0) * 4096;
    #pragma unroll
    for (int mt = 0; mt < 2; mt++)
        #pragma unroll
        for (int nt = 0; nt < 4; nt++){
            int r0 = wm*32 + mt*16 + gid;
            int cg = n0 + wn*32 + nt*8 + 2*tig;
            float2 h0 = *(const float2*)(Hb + (size_t)r0*D_ + cg);
            float2 h1 = *(const float2*)(Hb + (size_t)(r0+8)*D_ + cg);
            float* g0 = Gb + (size_t)r0*4096;
            float* g1 = Gb + (size_t)(r0+8)*4096;
            *(float2*)(g0 + 1024 + cg) = make_float2(acc[mt][nt][0], acc[mt][nt][1]);
            *(float2*)(g0 + 2048 + cg) = make_float2(acc[mt][nt][0]*h0.x, acc[mt][nt][1]*h0.y);
            *(float2*)(g1 + 1024 + cg) = make_float2(acc[mt][nt][2], acc[mt][nt][3]);
            *(float2*)(g1 + 2048 + cg) = make_float2(acc[mt][nt][2]*h1.x, acc[mt][nt][3]*h1.y);
        }
}

// -------- K2: att2 = softmax_t(rowmax) --------
__global__ void att2_kernel(float* __restrict__ out){
    __shared__ float red[8];
    int b = blockIdx.x, tid = threadIdx.x;
    float v[8];
    #pragma unroll
    for (int i = 0; i < 8; i++) v[i] = g_rowmax[b*T_ + tid + i*256];
    float mx = v[0];
    #pragma unroll
    for (int i = 1; i < 8; i++) mx = fmaxf(mx, v[i]);
    #pragma unroll
    for (int o = 16; o; o >>= 1) mx = fmaxf(mx, __shfl_xor_sync(0xffffffffu, mx, o));
    if ((tid & 31) == 0) red[tid >> 5] = mx;
    __syncthreads();
    mx = red[0];
    #pragma unroll
    for (int i = 1; i < 8; i++) mx = fmaxf(mx, red[i]);
    float e[8], s = 0.f;
    #pragma unroll
    for (int i = 0; i < 8; i++){ e[i] = __expf(v[i] - mx); s += e[i]; }
    #pragma unroll
    for (int o = 16; o; o >>= 1) s += __shfl_xor_sync(0xffffffffu, s, o);
    __syncthreads();
    if ((tid & 31) == 0) red[tid >> 5] = s;
    __syncthreads();
    s = 0.f;
    #pragma unroll
    for (int i = 0; i < 8; i++) s += red[i];
    float inv = 1.f / s;
    #pragma unroll
    for (int i = 0; i < 8; i++) out[OFF_ATT2 + b*T_ + tid + i*256] = e[i] * inv;
}

// -------- K3a: partial agg2 --------
__global__ __launch_bounds__(128)
void agg2p_kernel(const float* __restrict__ H, const float* __restrict__ out){
    int b  = blockIdx.z;
    int tc = blockIdx.y;
    int d4 = blockIdx.x * 128 + threadIdx.x;
    int t0 = tc * (T_/TCH);
    const float* a2 = out + OFF_ATT2 + b*T_ + t0;
    const float4* Hb = (const float4*)(H + ((size_t)b*T_ + t0) * D_) + d4;
    float4 acc = make_float4(0.f, 0.f, 0.f, 0.f);
    #pragma unroll 1
    for (int t = 0; t < T_/TCH; t += 8){
        #pragma unroll
        for (int u = 0; u < 8; u++){
            float a = a2[t+u];
            float4 h = Hb[(size_t)(t+u) * 256];
            acc.x += a*h.x; acc.y += a*h.y; acc.z += a*h.z; acc.w += a*h.w;
        }
    }
    ((float4*)g_agg2p)[((size_t)b*TCH + tc)*256 + d4] = acc;
}

// -------- K3b: reduce --------
__global__ void agg2r_kernel(){
    int idx = blockIdx.x * 256 + threadIdx.x;
    int b = idx >> 10, d = idx & 1023;
    const float* p = g_agg2p + (size_t)b*TCH*D_ + d;
    float acc = 0.f;
    #pragma unroll
    for (int c = 0; c < TCH; c++) acc += p[(size_t)c*D_];
    g_agg2[idx] = acc;
}

// -------- K4: G1 = H ; G4 = H .* agg2 --------
__global__ void g45_kernel(const float* __restrict__ H, float* __restrict__ out){
    int idx = blockIdx.x * 256 + threadIdx.x;
    int d4 = idx & 255;
    int bt = idx >> 8;
    int b  = bt >> 11;
    float4 h = ((const float4*)H)[idx];
    float4 a = ((const float4*)g_agg2)[b*256 + d4];
    float* Gb = out + OFF_G + (size_t)bt*4096;
    *(float4*)(Gb + d4*4) = h;
    *(float4*)(Gb + 3072 + d4*4) = make_float4(h.x*a.x, h.y*a.y, h.z*a.z, h.w*a.w);
}

extern "C" void kernel_launch(void* const* d_in, const int* in_sizes, int n_in,
                              void* d_out, int out_size){
    const float* H    = (const float*)d_in[0];
    const float* U    = (const float*)d_in[1];
    const float* w    = (const float*)d_in[2];
    const float* bias = (const float*)d_in[3];
    float* out = (float*)d_out;

    cudaFuncSetAttribute(scores_kernel, cudaFuncAttributeMaxDynamicSharedMemorySize, SC_TOT);
    cudaFuncSetAttribute(agg1_kernel, cudaFuncAttributeMaxDynamicSharedMemorySize, 49152);

    colterm_kernel<<<256, 256>>>(U, w, bias);
    uw3h_kernel<<<B_*J_*D_/4/256, 256>>>(U, w);
    uth_kernel<<<dim3(D_/32, J_/32, B_), dim3(32, 8)>>>(U);
    scores_kernel<<<dim3(T_/64, B_), 256, SC_TOT>>>(H, w, out);
    agg1_kernel<<<dim3(D_/64, T_/128, B_), 256, 49152>>>(H, out);
    att2_kernel<<<B_, 256>>>(out);
    agg2p_kernel<<<dim3(2, TCH, B_), 128>>>(H, out);
    agg2r_kernel<<<B_*D_/256, 256>>>();
    g45_kernel<<<(B_*T_*D_/4)/256, 256>>>(H, out);
}

// round 7
// speedup vs baseline: 1.7344x; 1.1640x over previous
#include <cuda_runtime.h>
#include <cuda_fp16.h>
#include <cstdint>

#define B_ 16
#define T_ 2048
#define J_ 128
#define D_ 1024

#define N_ATT1 (B_*T_*J_)
#define OFF_ATT2 N_ATT1
#define OFF_G (OFF_ATT2 + B_*T_)

#define TCH 32

// scores kernel smem map (bytes)
#define SC_BUF    0        // 2 x (Hh 8KB + UW 16KB) = 49152
#define SC_RED    49152    // 2*64*4 floats = 2KB
#define SC_WS     51200    // 4KB (w1)
#define SC_CTS    55296    // 512B
#define SC_HROW   55808    // 256B
#define SC_TOT    56320

#define SWZ8(r,c)  (((r)<<7) + (((c) ^ ((r)&7)) << 4))
#define SWZ16(r,c) (((r)<<8) + (((c) ^ ((r)&7)) << 4))

__device__ float g_colterm[B_*J_];
__device__ float g_rowmax[B_*T_];
__device__ float g_agg2[B_*D_];
__device__ float g_agg2p[B_*TCH*D_];
__device__ __half g_uw3h[B_*J_*D_];   // fp16 U .* w3   [b][j][d]
__device__ __half g_uth[B_*D_*J_];    // fp16 U^T       [b][d][j]
__device__ __half g_att1h[B_*T_*J_];  // fp16 att1      [b][t][j]

__device__ __forceinline__ uint32_t smem_u32(const void* p){
    uint32_t a;
    asm("{ .reg .u64 t; cvta.to.shared.u64 t, %1; cvt.u32.u64 %0, t; }" : "=r"(a) : "l"(p));
    return a;
}
__device__ __forceinline__ void cp16(uint32_t s, const void* g){
    asm volatile("cp.async.cg.shared.global [%0], [%1], 16;" :: "r"(s), "l"(g));
}
#define CP_COMMIT asm volatile("cp.async.commit_group;")
#define CP_WAIT0  asm volatile("cp.async.wait_group 0;")

__device__ __forceinline__ void ldm4(uint32_t r[4], uint32_t a){
    asm volatile("ldmatrix.sync.aligned.m8n8.x4.shared.b16 {%0,%1,%2,%3}, [%4];"
        : "=r"(r[0]), "=r"(r[1]), "=r"(r[2]), "=r"(r[3]) : "r"(a));
}
__device__ __forceinline__ void mma_f16(float c[4], const uint32_t a[4], uint32_t b0, uint32_t b1){
    asm volatile("mma.sync.aligned.m16n8k16.row.col.f32.f16.f16.f32 "
        "{%0,%1,%2,%3}, {%4,%5,%6,%7}, {%8,%9}, {%0,%1,%2,%3};"
        : "+f"(c[0]), "+f"(c[1]), "+f"(c[2]), "+f"(c[3])
        : "r"(a[0]), "r"(a[1]), "r"(a[2]), "r"(a[3]), "r"(b0), "r"(b1));
}

// -------- K0a: colterm --------
__global__ void colterm_kernel(const float* __restrict__ U, const float* __restrict__ w,
                               const float* __restrict__ bias){
    int pair = blockIdx.x * 8 + (threadIdx.x >> 5);
    int lane = threadIdx.x & 31;
    const float* u  = U + (size_t)pair * D_;
    const float* w2 = w + D_;
    float s = 0.f;
    for (int k = lane; k < D_; k += 32) s += u[k] * w2[k];
    #pragma unroll
    for (int o = 16; o; o >>= 1) s += __shfl_xor_sync(0xffffffffu, s, o);
    if (lane == 0) g_colterm[pair] = s + bias[0];
}

// -------- K0b: g_uw3h = fp16(U .* w3) --------
__global__ void uw3h_kernel(const float* __restrict__ U, const float* __restrict__ w){
    int idx = blockIdx.x * 256 + threadIdx.x;
    int d4 = idx & 255;
    float4 u = ((const float4*)U)[idx];
    float4 w3 = *(const float4*)(w + 2*D_ + d4*4);
    ((__half2*)g_uw3h)[idx*2]   = __floats2half2_rn(u.x*w3.x, u.y*w3.y);
    ((__half2*)g_uw3h)[idx*2+1] = __floats2half2_rn(u.z*w3.z, u.w*w3.w);
}

// -------- K0c: g_uth = fp16(U^T) per batch --------
__global__ void uth_kernel(const float* __restrict__ U){
    __shared__ float t[32][33];
    int b = blockIdx.z, j0 = blockIdx.y*32, d0 = blockIdx.x*32;
    int tx = threadIdx.x, ty = threadIdx.y;   // 32 x 8
    const float* Ub = U + ((size_t)b*J_ + j0)*D_ + d0;
    #pragma unroll
    for (int i = 0; i < 32; i += 8) t[ty+i][tx] = Ub[(size_t)(ty+i)*D_ + tx];
    __syncthreads();
    __half* Tb = g_uth + ((size_t)b*D_ + d0)*J_ + j0;
    #pragma unroll
    for (int i = 0; i < 32; i += 8) Tb[(size_t)(ty+i)*J_ + tx] = __float2half(t[tx][ty+i]);
}

// -------- K1: scores + register softmax --------
__global__ __launch_bounds__(256, 2)
void scores_kernel(const float* __restrict__ H, const float* __restrict__ w,
                   float* __restrict__ out){
    extern __shared__ char smc[];
    uint32_t smb = smem_u32(smc);
    float* red0 = (float*)(smc + SC_RED);            // [64][4]
    float* red1 = red0 + 256;                        // [64][4]
    float* ws   = (float*)(smc + SC_WS);
    float* cts  = (float*)(smc + SC_CTS);
    float* hrow = (float*)(smc + SC_HROW);

    int tid = threadIdx.x;
    int b = blockIdx.y, t0 = blockIdx.x * 64;
    int warp = tid >> 5, lane = tid & 31;
    int wm = warp >> 2, wn = warp & 3;
    int gid = lane >> 2, tig = lane & 3;
    int hr = tid >> 2, hq = tid & 3;

    const float*  Hb  = H + (size_t)(b*T_ + t0) * D_;
    const __half* UWb = g_uw3h + (size_t)b * J_ * D_;

    if (tid < 128) cts[tid] = g_colterm[b*J_ + tid];
    #pragma unroll
    for (int i = 0; i < 4; i++) ws[tid + i*256] = w[tid + i*256];

    // cp.async UW chunk 0
    {
        uint32_t dst = smb + 8192;
        int r = tid & 127, ch = tid >> 7;
        #pragma unroll
        for (int i = 0; i < 4; i++){
            int c16 = ch*4 + i;
            cp16(dst + SWZ8(r, c16), UWb + (size_t)r*D_ + c16*8);
        }
        CP_COMMIT;
    }
    float4 hreg[4];
    #pragma unroll
    for (int i = 0; i < 4; i++)
        hreg[i] = *(const float4*)(Hb + (size_t)hr*D_ + (hq + 4*i)*4);
    __syncthreads();

    float hp = 0.f;
    {   // STS H chunk0 (fp16) + hrow partial
        #pragma unroll
        for (int i = 0; i < 4; i++){
            int f4 = hq + 4*i;
            float4 h = hreg[i];
            __half2 p0 = __floats2half2_rn(h.x, h.y), p1 = __floats2half2_rn(h.z, h.w);
            uint32_t a = smb + SWZ8(hr, f4 >> 1) + (f4 & 1)*8;
            asm volatile("st.shared.v2.b32 [%0], {%1,%2};" :: "r"(a),
                         "r"(*(uint32_t*)&p0), "r"(*(uint32_t*)&p1));
            int wb = hq*4 + 16*i;
            hp += h.x*ws[wb] + h.y*ws[wb+1] + h.z*ws[wb+2] + h.w*ws[wb+3];
        }
    }

    float acc[2][4][4];
    #pragma unroll
    for (int i = 0; i < 2; i++)
        #pragma unroll
        for (int j = 0; j < 4; j++)
            #pragma unroll
            for (int k = 0; k < 4; k++) acc[i][j][k] = 0.f;

    // ---- S = H @ (U.*w3)^T, K=1024 in 16 chunks of 64 ----
    for (int kci = 0; kci < 16; kci++){
        int cur = kci & 1;
        if (kci < 15){
            #pragma unroll
            for (int i = 0; i < 4; i++)
                hreg[i] = *(const float4*)(Hb + (size_t)hr*D_ + (kci+1)*64 + (hq + 4*i)*4);
        }
        CP_WAIT0;
        __syncthreads();
        if (kci < 15){
            uint32_t dst = smb + (cur^1)*24576 + 8192;
            int r = tid & 127, ch = tid >> 7;
            #pragma unroll
            for (int i = 0; i < 4; i++){
                int c16 = ch*4 + i;
                cp16(dst + SWZ8(r, c16), UWb + (size_t)r*D_ + (kci+1)*64 + c16*8);
            }
            CP_COMMIT;
        }
        uint32_t bH = smb + cur*24576, bUW = bH + 8192;
        int lrow = lane & 15;
        #pragma unroll
        for (int kt = 0; kt < 4; kt++){
            int lc16 = kt*2 + (lane >> 4);
            uint32_t af[2][4], bf[2][4];
            ldm4(af[0], bH  + SWZ8(wm*32      + lrow, lc16));
            ldm4(af[1], bH  + SWZ8(wm*32 + 16 + lrow, lc16));
            ldm4(bf[0], bUW + SWZ8(wn*32      + lrow, lc16));
            ldm4(bf[1], bUW + SWZ8(wn*32 + 16 + lrow, lc16));
            #pragma unroll
            for (int mt = 0; mt < 2; mt++)
                #pragma unroll
                for (int nt = 0; nt < 4; nt++)
                    mma_f16(acc[mt][nt], af[mt], bf[nt>>1][nt&1], bf[nt>>1][(nt&1)+2]);
        }
        if (kci < 15){
            uint32_t bH2 = smb + (cur^1)*24576;
            #pragma unroll
            for (int i = 0; i < 4; i++){
                int f4 = hq + 4*i;
                float4 h = hreg[i];
                __half2 p0 = __floats2half2_rn(h.x, h.y), p1 = __floats2half2_rn(h.z, h.w);
                uint32_t a = bH2 + SWZ8(hr, f4 >> 1) + (f4 & 1)*8;
                asm volatile("st.shared.v2.b32 [%0], {%1,%2};" :: "r"(a),
                             "r"(*(uint32_t*)&p0), "r"(*(uint32_t*)&p1));
                int wb = (kci+1)*64 + hq*4 + 16*i;
                hp += h.x*ws[wb] + h.y*ws[wb+1] + h.z*ws[wb+2] + h.w*ws[wb+3];
            }
        }
    }
    hp += __shfl_xor_sync(0xffffffffu, hp, 1);
    hp += __shfl_xor_sync(0xffffffffu, hp, 2);
    __syncthreads();
    if (hq == 0) hrow[hr] = hp;

    // ---- register softmax ----
    int col0 = wn*32 + 2*tig;           // + nt*8
    #pragma unroll
    for (int mt = 0; mt < 2; mt++)
        #pragma unroll
        for (int nt = 0; nt < 4; nt++){
            acc[mt][nt][0] += cts[col0 + nt*8];
            acc[mt][nt][1] += cts[col0 + nt*8 + 1];
            acc[mt][nt][2] += cts[col0 + nt*8];
            acc[mt][nt][3] += cts[col0 + nt*8 + 1];
        }
    float rm[2][2];
    #pragma unroll
    for (int mt = 0; mt < 2; mt++)
        #pragma unroll
        for (int h = 0; h < 2; h++){
            float m = fmaxf(acc[mt][0][2*h], acc[mt][0][2*h+1]);
            #pragma unroll
            for (int nt = 1; nt < 4; nt++)
                m = fmaxf(m, fmaxf(acc[mt][nt][2*h], acc[mt][nt][2*h+1]));
            m = fmaxf(m, __shfl_xor_sync(0xffffffffu, m, 1));
            m = fmaxf(m, __shfl_xor_sync(0xffffffffu, m, 2));
            rm[mt][h] = m;
        }
    if (tig == 0){
        #pragma unroll
        for (int mt = 0; mt < 2; mt++)
            #pragma unroll
            for (int h = 0; h < 2; h++)
                red0[(wm*32 + mt*16 + h*8 + gid)*4 + wn] = rm[mt][h];
    }
    __syncthreads();
    float rs[2][2];
    #pragma unroll
    for (int mt = 0; mt < 2; mt++)
        #pragma unroll
        for (int h = 0; h < 2; h++){
            int r = wm*32 + mt*16 + h*8 + gid;
            float m = fmaxf(fmaxf(red0[r*4], red0[r*4+1]), fmaxf(red0[r*4+2], red0[r*4+3]));
            rm[mt][h] = m;
            float s = 0.f;
            #pragma unroll
            for (int nt = 0; nt < 4; nt++){
                acc[mt][nt][2*h]   = __expf(acc[mt][nt][2*h]   - m);
                acc[mt][nt][2*h+1] = __expf(acc[mt][nt][2*h+1] - m);
                s += acc[mt][nt][2*h] + acc[mt][nt][2*h+1];
            }
            s += __shfl_xor_sync(0xffffffffu, s, 1);
            s += __shfl_xor_sync(0xffffffffu, s, 2);
            rs[mt][h] = s;
        }
    if (tig == 0){
        #pragma unroll
        for (int mt = 0; mt < 2; mt++)
            #pragma unroll
            for (int h = 0; h < 2; h++)
                red1[(wm*32 + mt*16 + h*8 + gid)*4 + wn] = rs[mt][h];
    }
    __syncthreads();
    float* att1out = out + (size_t)(b*T_ + t0) * J_;
    #pragma unroll
    for (int mt = 0; mt < 2; mt++)
        #pragma unroll
        for (int h = 0; h < 2; h++){
            int r = wm*32 + mt*16 + h*8 + gid;
            float inv = 1.f / (red1[r*4] + red1[r*4+1] + red1[r*4+2] + red1[r*4+3]);
            #pragma unroll
            for (int nt = 0; nt < 4; nt++){
                float e0 = acc[mt][nt][2*h] * inv;
                float e1 = acc[mt][nt][2*h+1] * inv;
                int c = col0 + nt*8;
                *(float2*)(att1out + (size_t)r*J_ + c) = make_float2(e0, e1);
                *(__half2*)(g_att1h + (size_t)(b*T_ + t0 + r)*J_ + c) = __floats2half2_rn(e0, e1);
            }
            if (wn == 0 && tig == 0)
                g_rowmax[b*T_ + t0 + r] = rm[mt][h] + hrow[r];
        }
}

// -------- K1b: agg1 = att1 @ U + full G epilogue (G1..G4) --------
__global__ __launch_bounds__(256, 3)
void agg1g_kernel(const float* __restrict__ H, float* __restrict__ out){
    extern __shared__ char smc[];
    uint32_t smb = smem_u32(smc);
    float* stage = (float*)smc;      // 128 x 68 fp32, overlays A/B after mma
    int tid = threadIdx.x;
    int b  = blockIdx.z;
    int m0 = blockIdx.y * 128;       // t rows
    int n0 = blockIdx.x * 64;        // d cols
    int warp = tid >> 5, lane = tid & 31;
    int wm = warp >> 1, wn = warp & 1;
    int gid = lane >> 2, tig = lane & 3;

    const __half* Ab = g_att1h + (size_t)(b*T_ + m0) * J_;
    const __half* Bb = g_uth + ((size_t)b*D_ + n0) * J_;

    // load A tile 128x128 fp16 (32KB) + B tile 64x128 fp16 (16KB)
    #pragma unroll
    for (int i = 0; i < 8; i++){
        int idx = tid + i*256;       // < 2048
        int r = idx >> 4, c = idx & 15;
        cp16(smb + SWZ16(r, c), Ab + (size_t)r*J_ + c*8);
    }
    #pragma unroll
    for (int i = 0; i < 4; i++){
        int idx = tid + i*256;       // < 1024
        int r = idx >> 4, c = idx & 15;
        cp16(smb + 32768 + SWZ16(r, c), Bb + (size_t)r*J_ + c*8);
    }
    CP_COMMIT;

    float acc[2][4][4];
    #pragma unroll
    for (int i = 0; i < 2; i++)
        #pragma unroll
        for (int j = 0; j < 4; j++)
            #pragma unroll
            for (int k = 0; k < 4; k++) acc[i][j][k] = 0.f;

    CP_WAIT0;
    __syncthreads();

    int lrow = lane & 15;
    uint32_t aB = smb, bB = smb + 32768;
    #pragma unroll
    for (int kt = 0; kt < 8; kt++){
        int lc16 = kt*2 + (lane >> 4);
        uint32_t af[2][4], bf[2][4];
        ldm4(af[0], aB + SWZ16(wm*32      + lrow, lc16));
        ldm4(af[1], aB + SWZ16(wm*32 + 16 + lrow, lc16));
        ldm4(bf[0], bB + SWZ16(wn*32      + lrow, lc16));
        ldm4(bf[1], bB + SWZ16(wn*32 + 16 + lrow, lc16));
        #pragma unroll
        for (int mt = 0; mt < 2; mt++)
            #pragma unroll
            for (int nt = 0; nt < 4; nt++)
                mma_f16(acc[mt][nt], af[mt], bf[nt>>1][nt&1], bf[nt>>1][(nt&1)+2]);
    }
    __syncthreads();                  // smem tiles no longer needed

    // stage agg1 fragments (stride 68: conflict-free for both passes)
    #pragma unroll
    for (int mt = 0; mt < 2; mt++)
        #pragma unroll
        for (int nt = 0; nt < 4; nt++){
            int r0 = wm*32 + mt*16 + gid;
            int c  = wn*32 + nt*8 + 2*tig;
            *(float2*)(stage + r0*68 + c)     = make_float2(acc[mt][nt][0], acc[mt][nt][1]);
            *(float2*)(stage + (r0+8)*68 + c) = make_float2(acc[mt][nt][2], acc[mt][nt][3]);
        }
    __syncthreads();

    // coalesced pass: G1 = H, G2 = agg1, G3 = H*agg1, G4 = H*agg2
    const float* Hb = H + (size_t)(b*T_ + m0) * D_ + n0;
    const float* A2 = g_agg2 + b*D_ + n0;
    float* Gb = out + OFF_G + (size_t)(b*T_ + m0) * 4096 + n0;
    #pragma unroll
    for (int it = 0; it < 8; it++){
        int idx = tid + it*256;       // < 2048
        int r = idx >> 4, c4 = (idx & 15)*4;
        float4 a1 = *(float4*)(stage + r*68 + c4);
        float4 h  = *(const float4*)(Hb + (size_t)r*D_ + c4);
        float4 a2 = *(const float4*)(A2 + c4);
        float* g = Gb + (size_t)r*4096 + c4;
        *(float4*)(g)        = h;
        *(float4*)(g + 1024) = a1;
        *(float4*)(g + 2048) = make_float4(a1.x*h.x, a1.y*h.y, a1.z*h.z, a1.w*h.w);
        *(float4*)(g + 3072) = make_float4(h.x*a2.x, h.y*a2.y, h.z*a2.z, h.w*a2.w);
    }
}

// -------- K2: att2 = softmax_t(rowmax) --------
__global__ void att2_kernel(float* __restrict__ out){
    __shared__ float red[8];
    int b = blockIdx.x, tid = threadIdx.x;
    float v[8];
    #pragma unroll
    for (int i = 0; i < 8; i++) v[i] = g_rowmax[b*T_ + tid + i*256];
    float mx = v[0];
    #pragma unroll
    for (int i = 1; i < 8; i++) mx = fmaxf(mx, v[i]);
    #pragma unroll
    for (int o = 16; o; o >>= 1) mx = fmaxf(mx, __shfl_xor_sync(0xffffffffu, mx, o));
    if ((tid & 31) == 0) red[tid >> 5] = mx;
    __syncthreads();
    mx = red[0];
    #pragma unroll
    for (int i = 1; i < 8; i++) mx = fmaxf(mx, red[i]);
    float e[8], s = 0.f;
    #pragma unroll
    for (int i = 0; i < 8; i++){ e[i] = __expf(v[i] - mx); s += e[i]; }
    #pragma unroll
    for (int o = 16; o; o >>= 1) s += __shfl_xor_sync(0xffffffffu, s, o);
    __syncthreads();
    if ((tid & 31) == 0) red[tid >> 5] = s;
    __syncthreads();
    s = 0.f;
    #pragma unroll
    for (int i = 0; i < 8; i++) s += red[i];
    float inv = 1.f / s;
    #pragma unroll
    for (int i = 0; i < 8; i++) out[OFF_ATT2 + b*T_ + tid + i*256] = e[i] * inv;
}

// -------- K3a: partial agg2 --------
__global__ __launch_bounds__(128)
void agg2p_kernel(const float* __restrict__ H, const float* __restrict__ out){
    int b  = blockIdx.z;
    int tc = blockIdx.y;
    int d4 = blockIdx.x * 128 + threadIdx.x;
    int t0 = tc * (T_/TCH);
    const float* a2 = out + OFF_ATT2 + b*T_ + t0;
    const float4* Hb = (const float4*)(H + ((size_t)b*T_ + t0) * D_) + d4;
    float4 acc = make_float4(0.f, 0.f, 0.f, 0.f);
    #pragma unroll 1
    for (int t = 0; t < T_/TCH; t += 8){
        #pragma unroll
        for (int u = 0; u < 8; u++){
            float a = a2[t+u];
            float4 h = Hb[(size_t)(t+u) * 256];
            acc.x += a*h.x; acc.y += a*h.y; acc.z += a*h.z; acc.w += a*h.w;
        }
    }
    ((float4*)g_agg2p)[((size_t)b*TCH + tc)*256 + d4] = acc;
}

// -------- K3b: reduce --------
__global__ void agg2r_kernel(){
    int idx = blockIdx.x * 256 + threadIdx.x;
    int b = idx >> 10, d = idx & 1023;
    const float* p = g_agg2p + (size_t)b*TCH*D_ + d;
    float acc = 0.f;
    #pragma unroll
    for (int c = 0; c < TCH; c++) acc += p[(size_t)c*D_];
    g_agg2[idx] = acc;
}

extern "C" void kernel_launch(void* const* d_in, const int* in_sizes, int n_in,
                              void* d_out, int out_size){
    const float* H    = (const float*)d_in[0];
    const float* U    = (const float*)d_in[1];
    const float* w    = (const float*)d_in[2];
    const float* bias = (const float*)d_in[3];
    float* out = (float*)d_out;

    cudaFuncSetAttribute(scores_kernel, cudaFuncAttributeMaxDynamicSharedMemorySize, SC_TOT);
    cudaFuncSetAttribute(agg1g_kernel, cudaFuncAttributeMaxDynamicSharedMemorySize, 49152);

    colterm_kernel<<<256, 256>>>(U, w, bias);
    uw3h_kernel<<<B_*J_*D_/4/256, 256>>>(U, w);
    uth_kernel<<<dim3(D_/32, J_/32, B_), dim3(32, 8)>>>(U);
    scores_kernel<<<dim3(T_/64, B_), 256, SC_TOT>>>(H, w, out);
    att2_kernel<<<B_, 256>>>(out);
    agg2p_kernel<<<dim3(2, TCH, B_), 128>>>(H, out);
    agg2r_kernel<<<B_*D_/256, 256>>>();
    agg1g_kernel<<<dim3(D_/64, T_/128, B_), 256, 49152>>>(H, out);
}